// round 3
// baseline (speedup 1.0000x reference)
#include <cuda_runtime.h>
#include <cstdint>
#include <cfloat>

#define B_  32
#define K_  17
#define H_  192
#define W_  192
#define C_  19
#define P_  20
#define S_  10
#define HW_ (H_*W_)
#define NCH (B_*K_)

#define PEAK_THRESH      0.1f
#define PAF_SCORE_THRESH 0.05f
#define PAF_COUNT_THRESH 0.8f

#define NT1      256
#define TROWS    16
#define TILE_R   (TROWS + 2)
#define NTILES   (H_ / TROWS)
#define CAND_CAP 5120
#define SURV_CAP 512
#define NBINS    256

__constant__ int SKEL_A[C_] = {15,13,16,14,11, 5, 6, 5, 5, 6, 7, 8, 1, 0, 0, 1, 2, 3, 4};
__constant__ int SKEL_B[C_] = {13,11,14,12,12,11,12, 6, 7, 8, 9,10, 2, 1, 2, 3, 4, 5, 6};

// global scratch (allowed: __device__ arrays)
__device__ unsigned long long g_keys[NCH][CAND_CAP];   // ~22.3 MB
__device__ int g_count[NCH];
__device__ int g_hist[NCH][NBINS];

__device__ __forceinline__ float fmax3(float a, float b, float c) {
    return fmaxf(a, fmaxf(b, c));
}

// ---------------------------------------------------------------------------
// Kernel 0: zero counters + histograms.
// ---------------------------------------------------------------------------
__global__ void init_kernel()
{
    int n = NCH * (NBINS + 1);
    for (int i = blockIdx.x * blockDim.x + threadIdx.x; i < n;
         i += gridDim.x * blockDim.x) {
        if (i < NCH) g_count[i] = 0;
        else {
            int j = i - NCH;
            g_hist[j / NBINS][j % NBINS] = 0;
        }
    }
}

// ---------------------------------------------------------------------------
// Kernel 1a: streaming peak scan. One CTA per (tile, channel).
// ---------------------------------------------------------------------------
__global__ __launch_bounds__(NT1)
void peaks_scan(const float* __restrict__ heat)
{
    const int tile = blockIdx.x;
    const int bk   = blockIdx.y;
    const float* __restrict__ h = heat + (size_t)bk * HW_;
    const int ybase = tile * TROWS;

    __shared__ float vt[TILE_R][W_];
    __shared__ float hm[TILE_R][W_];

    const int tid  = threadIdx.x;
    const int lane = tid & 31;

    // --- load 18 rows (ybase-1 .. ybase+16) as float4 ---
    for (int i = tid; i < TILE_R * (W_/4); i += NT1) {
        int r  = i / (W_/4);
        int g  = i - r * (W_/4);
        int gy = ybase - 1 + r;
        float4 val;
        if (gy >= 0 && gy < H_)
            val = __ldg((const float4*)(h + (size_t)gy * W_) + g);
        else
            val = make_float4(-FLT_MAX, -FLT_MAX, -FLT_MAX, -FLT_MAX);
        *(float4*)&vt[r][g*4] = val;
    }
    __syncthreads();

    // --- horizontal 3-max ---
    for (int i = tid; i < TILE_R * (W_/4); i += NT1) {
        int r = i / (W_/4);
        int g = i - r * (W_/4);
        float4 c = *(const float4*)&vt[r][g*4];
        float left  = (g > 0)        ? vt[r][g*4 - 1] : -FLT_MAX;
        float right = (g < W_/4 - 1) ? vt[r][g*4 + 4] : -FLT_MAX;
        float4 o;
        o.x = fmax3(left, c.x, c.y);
        o.y = fmax3(c.x, c.y, c.z);
        o.z = fmax3(c.y, c.z, c.w);
        o.w = fmax3(c.z, c.w, right);
        *(float4*)&hm[r][g*4] = o;
    }
    __syncthreads();

    // --- peak test: uniform trip count 16*48/256 = 3 (all lanes active) ---
    for (int i = tid; i < TROWS * (W_/4); i += NT1) {
        int gy = i / (W_/4);
        int g  = i - gy * (W_/4);
        int ty = gy + 1;

        float4 v  = *(const float4*)&vt[ty][g*4];
        float4 m0 = *(const float4*)&hm[ty-1][g*4];
        float4 m1 = *(const float4*)&hm[ty  ][g*4];
        float4 m2 = *(const float4*)&hm[ty+1][g*4];

        float vv[4] = {v.x, v.y, v.z, v.w};
        float mm[4] = {fmax3(m0.x, m1.x, m2.x), fmax3(m0.y, m1.y, m2.y),
                       fmax3(m0.z, m1.z, m2.z), fmax3(m0.w, m1.w, m2.w)};

        const int prow = (ybase + gy) * W_ + g * 4;
        #pragma unroll
        for (int c = 0; c < 4; c++) {
            bool pk = (vv[c] > PEAK_THRESH) && (vv[c] >= mm[c]);
            unsigned m = __ballot_sync(0xffffffffu, pk);
            if (m == 0u) continue;
            int n = __popc(m);
            int base = 0;
            if (lane == 0) base = atomicAdd(&g_count[bk], n);
            base = __shfl_sync(0xffffffffu, base, 0);
            if (pk) {
                int pos = base + __popc(m & ((1u << lane) - 1u));
                if (pos < CAND_CAP) {
                    int p = prow + c;
                    g_keys[bk][pos] =
                        ((unsigned long long)__float_as_uint(vv[c]) << 32)
                        | (unsigned)(0xFFFFFFFFu - (unsigned)p);
                    int bin = min(NBINS - 1, (int)(vv[c] * (float)NBINS));
                    atomicAdd(&g_hist[bk][bin], 1);   // RED, no return
                }
            }
        }
    }
}

// ---------------------------------------------------------------------------
// Kernel 1b: per-channel top-20 selection + subpixel refine.
// ---------------------------------------------------------------------------
__global__ __launch_bounds__(NT1)
void peaks_select(const float* __restrict__ heat, float* __restrict__ out_peaks)
{
    const int bk = blockIdx.x;
    const float* __restrict__ h = heat + (size_t)bk * HW_;

    __shared__ unsigned long long surv[SURV_CAP];
    __shared__ int   s_nsurv, s_tbin;
    __shared__ unsigned long long w_key[NT1/32];
    __shared__ int   w_slot[NT1/32];
    __shared__ unsigned long long sel_key[P_];

    const int tid  = threadIdx.x;
    const int lane = tid & 31;
    const int wid  = tid >> 5;

    const int nc = min(g_count[bk], CAND_CAP);

    if (tid == 0) {
        s_nsurv = 0;
        int need = min(P_, nc);
        int cum = 0, t = 0;
        if (need > 0) {
            const int* hist = g_hist[bk];
            for (int b = NBINS - 1; b >= 0; --b) {
                cum += hist[b];
                if (cum >= need) { t = b; break; }
            }
        }
        s_tbin = t;
    }
    __syncthreads();
    const int tbin = s_tbin;

    for (int i = tid; i < nc; i += NT1) {
        unsigned long long k = g_keys[bk][i];
        float sc = __uint_as_float((unsigned)(k >> 32));
        int bin = min(NBINS - 1, (int)(sc * (float)NBINS));
        if (bin >= tbin) {
            int slot = atomicAdd(&s_nsurv, 1);
            if (slot < SURV_CAP) surv[slot] = k;
        }
    }
    __syncthreads();

    unsigned long long* list;
    int len;
    bool global_list = (s_nsurv > SURV_CAP);
    if (!global_list) { list = surv; len = s_nsurv; }
    else              { list = &g_keys[bk][0]; len = nc; }  // rare fallback

    for (int r = 0; r < P_; r++) {
        unsigned long long bkey = 0ull;
        int bslot = -1;
        for (int i = tid; i < len; i += NT1) {
            unsigned long long k = list[i];
            if (k > bkey) { bkey = k; bslot = i; }
        }
        #pragma unroll
        for (int o = 16; o > 0; o >>= 1) {
            unsigned long long ok = __shfl_down_sync(0xffffffffu, bkey, o);
            int os = __shfl_down_sync(0xffffffffu, bslot, o);
            if (ok > bkey) { bkey = ok; bslot = os; }
        }
        if (lane == 0) { w_key[wid] = bkey; w_slot[wid] = bslot; }
        __syncthreads();
        if (tid == 0) {
            unsigned long long best = 0ull; int bsl = -1;
            #pragma unroll
            for (int w = 0; w < NT1/32; w++)
                if (w_key[w] > best) { best = w_key[w]; bsl = w_slot[w]; }
            sel_key[r] = best;
            if (bsl >= 0) list[bsl] = 0ull;
        }
        __syncthreads();
    }

    if (tid < P_) {
        unsigned long long k = sel_key[tid];
        float px = 0.0f, py = 0.0f, so = 0.0f;
        if (k != 0ull) {
            float sc = __uint_as_float((unsigned)(k >> 32));
            int p = (int)(0xFFFFFFFFu - (unsigned)(k & 0xFFFFFFFFull));
            int y = p / W_;
            int x = p - y * W_;
            float ddx = 0.0f, ddy = 0.0f;
            if (x > 0 && x < W_-1 && y > 0 && y < H_-1) {
                float c  = h[p];
                float rr = h[p + 1],  ll = h[p - 1];
                float dd = h[p + W_], uu = h[p - W_];
                float dx  = 0.5f * (rr - ll);
                float dxx = (rr + ll) - 2.0f * c;
                if (dxx != 0.0f) dx = dx / (-dxx);
                float dy  = 0.5f * (dd - uu);
                float dyy = (dd + uu) - 2.0f * c;
                if (dyy != 0.0f) dy = dy / (-dyy);
                ddx = dx; ddy = dy;
            }
            px = (float)x + ddx;
            py = (float)y + ddy;
            so = sc;
        }
        float* o = out_peaks + ((size_t)bk * P_ + tid) * 3;
        o[0] = px; o[1] = py; o[2] = so;
    }
}

// ---------------------------------------------------------------------------
// Kernel 2: per (b,c) edge — PAF line-integral scoring.
// ---------------------------------------------------------------------------
#define NT2 416
__global__ __launch_bounds__(NT2)
void conn_kernel(const float* __restrict__ paf,
                 const float* __restrict__ peaks,
                 float* __restrict__ conn)
{
    const int c = blockIdx.x;
    const int b = blockIdx.y;

    __shared__ float ax[P_], ay[P_], sa[P_];
    __shared__ float bx[P_], by[P_], sb[P_];

    const int tid = threadIdx.x;
    if (tid < 2 * P_) {
        int j = (tid < P_) ? tid : tid - P_;
        int joint = (tid < P_) ? SKEL_A[c] : SKEL_B[c];
        const float* pk = peaks + (((size_t)b * K_ + joint) * P_ + j) * 3;
        float x = pk[0], y = pk[1], s = pk[2];
        if (tid < P_) { ax[j] = x; ay[j] = y; sa[j] = s; }
        else          { bx[j] = x; by[j] = y; sb[j] = s; }
    }
    __syncthreads();

    if (tid >= P_ * P_) return;

    const float* __restrict__ pafx = paf + ((size_t)b * (2*C_) + 2*c) * HW_;
    const float* __restrict__ pafy = pafx + HW_;

    const float delta = 1.0f / 9.0f;

    const int i = tid / P_;
    const int j = tid - i * P_;

    float axi = ax[i], ayi = ay[i];
    float dxl = bx[j] - axi;
    float dyl = by[j] - ayi;
    float norm = sqrtf(dxl*dxl + dyl*dyl) + 1e-8f;
    float vx = dxl / norm, vy = dyl / norm;

    int   idx[S_];
    bool  inb[S_];
    #pragma unroll
    for (int s = 0; s < S_; s++) {
        float t = (s == S_-1) ? 1.0f : (float)s * delta;
        float xs = axi + dxl * t;
        float ys = ayi + dyl * t;
        int xi = __float2int_rz(xs);
        int yi = __float2int_rz(ys);
        inb[s] = (xi >= 0) & (xi < W_) & (yi >= 0) & (yi < H_);
        int xc = min(max(xi, 0), W_ - 1);
        int yc = min(max(yi, 0), H_ - 1);
        idx[s] = yc * W_ + xc;
    }

    float pxv[S_], pyv[S_];
    #pragma unroll
    for (int s = 0; s < S_; s++) pxv[s] = __ldg(pafx + idx[s]);
    #pragma unroll
    for (int s = 0; s < S_; s++) pyv[s] = __ldg(pafy + idx[s]);

    float cnt = 0.0f, sum = 0.0f, cntp = 0.0f;
    #pragma unroll
    for (int s = 0; s < S_; s++) {
        float vs = pxv[s] * vx + pyv[s] * vy;
        if (inb[s]) {
            cnt += 1.0f;
            sum += vs;
            if (vs > PAF_SCORE_THRESH) cntp += 1.0f;
        }
    }

    float denom = fmaxf(cnt, 1.0f);
    float mean  = sum / denom;
    float ratio = cntp / denom;
    bool ok = (cnt > 0.0f) && (mean > 0.0f) && (ratio > PAF_COUNT_THRESH)
              && (sa[i] > PEAK_THRESH) && (sb[j] > PEAK_THRESH);
    float val = ok ? (mean + 0.5f * (sa[i] + sb[j])) : 0.0f;
    conn[(((size_t)b * C_ + c) * P_ + i) * P_ + j] = val;
}

// ---------------------------------------------------------------------------
extern "C" void kernel_launch(void* const* d_in, const int* in_sizes, int n_in,
                              void* d_out, int out_size)
{
    const float* heat = (const float*)d_in[0];
    const float* paf  = (const float*)d_in[1];
    if (n_in >= 2 && in_sizes[0] == B_ * 2 * C_ * HW_ && in_sizes[1] == B_ * K_ * HW_) {
        heat = (const float*)d_in[1];
        paf  = (const float*)d_in[0];
    }

    float* out_peaks = (float*)d_out;                      // B*K*P*3
    float* out_conn  = out_peaks + (size_t)B_ * K_ * P_ * 3;

    init_kernel<<<148, 256>>>();

    dim3 g1(NTILES, NCH);
    peaks_scan<<<g1, NT1>>>(heat);

    peaks_select<<<NCH, NT1>>>(heat, out_peaks);

    dim3 g2(C_, B_);
    conn_kernel<<<g2, NT2>>>(paf, out_peaks, out_conn);
}

// round 4
// speedup vs baseline: 2.2924x; 2.2924x over previous
#include <cuda_runtime.h>
#include <cstdint>
#include <cfloat>

#define B_  32
#define K_  17
#define H_  192
#define W_  192
#define C_  19
#define P_  20
#define S_  10
#define HW_ (H_*W_)
#define NCH (B_*K_)

#define PEAK_THRESH      0.1f
#define PAF_SCORE_THRESH 0.05f
#define PAF_COUNT_THRESH 0.8f

#define CAND_CAP 5120
#define SURV_CAP 512
#define NBINS    256
#define CTA_BUF  512      // per-CTA candidate staging (expect ~154)

#define QX  48            // quads per row (192/4)
#define RY  8             // rows per CTA
#define NTS (QX*RY)       // 384 threads

__constant__ int SKEL_A[C_] = {15,13,16,14,11, 5, 6, 5, 5, 6, 7, 8, 1, 0, 0, 1, 2, 3, 4};
__constant__ int SKEL_B[C_] = {13,11,14,12,12,11,12, 6, 7, 8, 9,10, 2, 1, 2, 3, 4, 5, 6};

// global scratch (zero-initialized at load; select restores zeros each run)
__device__ unsigned long long g_keys[NCH][CAND_CAP];
__device__ int g_count[NCH];
__device__ int g_hist[NCH][NBINS];

__device__ __forceinline__ float fmax3(float a, float b, float c) {
    return fmaxf(a, fmaxf(b, c));
}

// ---------------------------------------------------------------------------
// Kernel 1a: barrier-free streaming peak scan. Thread = one float4 quad.
// ---------------------------------------------------------------------------
__global__ __launch_bounds__(NTS)
void peaks_scan(const float* __restrict__ heat)
{
    const int bk = blockIdx.y;
    const float* __restrict__ h = heat + (size_t)bk * HW_;

    const int qx = threadIdx.x;                    // 0..47
    const int y  = blockIdx.x * RY + threadIdx.y;  // 0..191
    const int tid  = threadIdx.y * QX + threadIdx.x;
    const int lane = tid & 31;

    __shared__ unsigned long long s_buf[CTA_BUF];
    __shared__ int s_hist[NBINS];
    __shared__ int s_cnt;
    __shared__ int s_gbase;

    for (int i = tid; i < NBINS; i += NTS) s_hist[i] = 0;
    if (tid == 0) s_cnt = 0;
    __syncthreads();

    const bool up_ok = (y > 0);
    const bool dn_ok = (y < H_ - 1);
    const float* r1 = h + (size_t)y * W_;
    const float* r0 = r1 - W_;
    const float* r2 = r1 + W_;
    const int x0 = qx * 4;

    const float4 NEG4 = make_float4(-FLT_MAX, -FLT_MAX, -FLT_MAX, -FLT_MAX);

    float4 c1 = __ldg((const float4*)r1 + qx);
    float4 c0 = up_ok ? __ldg((const float4*)r0 + qx) : NEG4;
    float4 c2 = dn_ok ? __ldg((const float4*)r2 + qx) : NEG4;

    float l0 = -FLT_MAX, l1 = -FLT_MAX, l2 = -FLT_MAX;
    float rr0 = -FLT_MAX, rr1 = -FLT_MAX, rr2 = -FLT_MAX;
    if (qx > 0) {
        l1 = __ldg(r1 + x0 - 1);
        if (up_ok) l0 = __ldg(r0 + x0 - 1);
        if (dn_ok) l2 = __ldg(r2 + x0 - 1);
    }
    if (qx < QX - 1) {
        rr1 = __ldg(r1 + x0 + 4);
        if (up_ok) rr0 = __ldg(r0 + x0 + 4);
        if (dn_ok) rr2 = __ldg(r2 + x0 + 4);
    }

    // vertical 3-max per column, then horizontal 3-window
    float vl = fmax3(l0, l1, l2);
    float vr = fmax3(rr0, rr1, rr2);
    float vmx = fmax3(c0.x, c1.x, c2.x);
    float vmy = fmax3(c0.y, c1.y, c2.y);
    float vmz = fmax3(c0.z, c1.z, c2.z);
    float vmw = fmax3(c0.w, c1.w, c2.w);

    float wm[4];
    wm[0] = fmax3(vl,  vmx, vmy);
    wm[1] = fmax3(vmx, vmy, vmz);
    wm[2] = fmax3(vmy, vmz, vmw);
    wm[3] = fmax3(vmz, vmw, vr);
    float vv[4] = {c1.x, c1.y, c1.z, c1.w};

    const int prow = y * W_ + x0;
    #pragma unroll
    for (int c = 0; c < 4; c++) {
        bool pk = (vv[c] > PEAK_THRESH) && (vv[c] >= wm[c]);
        unsigned m = __ballot_sync(0xffffffffu, pk);
        if (m == 0u) continue;
        int base = 0;
        if (lane == 0) base = atomicAdd(&s_cnt, __popc(m));
        base = __shfl_sync(0xffffffffu, base, 0);
        if (pk) {
            int pos = base + __popc(m & ((1u << lane) - 1u));
            if (pos < CTA_BUF) {
                int p = prow + c;
                s_buf[pos] = ((unsigned long long)__float_as_uint(vv[c]) << 32)
                           | (unsigned)(0xFFFFFFFFu - (unsigned)p);
                int bin = min(NBINS - 1, (int)(vv[c] * (float)NBINS));
                atomicAdd(&s_hist[bin], 1);
            }
        }
    }
    __syncthreads();

    const int n = min(s_cnt, CTA_BUF);
    if (tid == 0 && n > 0) s_gbase = atomicAdd(&g_count[bk], n);
    __syncthreads();

    if (n > 0) {
        const int gbase = s_gbase;
        for (int i = tid; i < n; i += NTS) {
            int pos = gbase + i;
            if (pos < CAND_CAP) g_keys[bk][pos] = s_buf[i];
        }
    }
    for (int i = tid; i < NBINS; i += NTS) {
        int hv = s_hist[i];
        if (hv) atomicAdd(&g_hist[bk][i], hv);   // fire-and-forget RED
    }
}

// ---------------------------------------------------------------------------
// Kernel 1b: per-channel top-20 selection + subpixel refine + scratch reset.
// ---------------------------------------------------------------------------
#define NT1 256
__global__ __launch_bounds__(NT1)
void peaks_select(const float* __restrict__ heat, float* __restrict__ out_peaks)
{
    const int bk = blockIdx.x;
    const float* __restrict__ h = heat + (size_t)bk * HW_;

    __shared__ unsigned long long surv[SURV_CAP];
    __shared__ int   s_nsurv, s_tbin;
    __shared__ unsigned long long w_key[NT1/32];
    __shared__ int   w_slot[NT1/32];
    __shared__ unsigned long long sel_key[P_];

    const int tid  = threadIdx.x;
    const int lane = tid & 31;
    const int wid  = tid >> 5;

    const int nc = min(g_count[bk], CAND_CAP);

    if (tid == 0) {
        s_nsurv = 0;
        int need = min(P_, nc);
        int cum = 0, t = 0;
        if (need > 0) {
            const int* hist = g_hist[bk];
            for (int b = NBINS - 1; b >= 0; --b) {
                cum += hist[b];
                if (cum >= need) { t = b; break; }
            }
        }
        s_tbin = t;
    }
    __syncthreads();
    const int tbin = s_tbin;

    for (int i = tid; i < nc; i += NT1) {
        unsigned long long k = g_keys[bk][i];
        float sc = __uint_as_float((unsigned)(k >> 32));
        int bin = min(NBINS - 1, (int)(sc * (float)NBINS));
        if (bin >= tbin) {
            int slot = atomicAdd(&s_nsurv, 1);
            if (slot < SURV_CAP) surv[slot] = k;
        }
    }
    __syncthreads();

    unsigned long long* list;
    int len;
    if (s_nsurv <= SURV_CAP) { list = surv; len = s_nsurv; }
    else                     { list = &g_keys[bk][0]; len = nc; }  // fallback

    for (int r = 0; r < P_; r++) {
        unsigned long long bkey = 0ull;
        int bslot = -1;
        for (int i = tid; i < len; i += NT1) {
            unsigned long long k = list[i];
            if (k > bkey) { bkey = k; bslot = i; }
        }
        #pragma unroll
        for (int o = 16; o > 0; o >>= 1) {
            unsigned long long ok = __shfl_down_sync(0xffffffffu, bkey, o);
            int os = __shfl_down_sync(0xffffffffu, bslot, o);
            if (ok > bkey) { bkey = ok; bslot = os; }
        }
        if (lane == 0) { w_key[wid] = bkey; w_slot[wid] = bslot; }
        __syncthreads();
        if (tid == 0) {
            unsigned long long best = 0ull; int bsl = -1;
            #pragma unroll
            for (int w = 0; w < NT1/32; w++)
                if (w_key[w] > best) { best = w_key[w]; bsl = w_slot[w]; }
            sel_key[r] = best;
            if (bsl >= 0) list[bsl] = 0ull;
        }
        __syncthreads();
    }

    if (tid < P_) {
        unsigned long long k = sel_key[tid];
        float px = 0.0f, py = 0.0f, so = 0.0f;
        if (k != 0ull) {
            float sc = __uint_as_float((unsigned)(k >> 32));
            int p = (int)(0xFFFFFFFFu - (unsigned)(k & 0xFFFFFFFFull));
            int y = p / W_;
            int x = p - y * W_;
            float ddx = 0.0f, ddy = 0.0f;
            if (x > 0 && x < W_-1 && y > 0 && y < H_-1) {
                float c  = h[p];
                float rr = h[p + 1],  ll = h[p - 1];
                float dd = h[p + W_], uu = h[p - W_];
                float dx  = 0.5f * (rr - ll);
                float dxx = (rr + ll) - 2.0f * c;
                if (dxx != 0.0f) dx = dx / (-dxx);
                float dy  = 0.5f * (dd - uu);
                float dyy = (dd + uu) - 2.0f * c;
                if (dyy != 0.0f) dy = dy / (-dyy);
                ddx = dx; ddy = dy;
            }
            px = (float)x + ddx;
            py = (float)y + ddy;
            so = sc;
        }
        float* o = out_peaks + ((size_t)bk * P_ + tid) * 3;
        o[0] = px; o[1] = py; o[2] = so;
    }

    // reset scratch for the next (graph-replayed) run
    if (tid == 0) g_count[bk] = 0;
    if (tid < NBINS) g_hist[bk][tid] = 0;
}

// ---------------------------------------------------------------------------
// Kernel 2: per (b,c) edge — PAF line-integral scoring.
// ---------------------------------------------------------------------------
#define NT2 416
__global__ __launch_bounds__(NT2)
void conn_kernel(const float* __restrict__ paf,
                 const float* __restrict__ peaks,
                 float* __restrict__ conn)
{
    const int c = blockIdx.x;
    const int b = blockIdx.y;

    __shared__ float ax[P_], ay[P_], sa[P_];
    __shared__ float bx[P_], by[P_], sb[P_];

    const int tid = threadIdx.x;
    if (tid < 2 * P_) {
        int j = (tid < P_) ? tid : tid - P_;
        int joint = (tid < P_) ? SKEL_A[c] : SKEL_B[c];
        const float* pk = peaks + (((size_t)b * K_ + joint) * P_ + j) * 3;
        float x = pk[0], y = pk[1], s = pk[2];
        if (tid < P_) { ax[j] = x; ay[j] = y; sa[j] = s; }
        else          { bx[j] = x; by[j] = y; sb[j] = s; }
    }
    __syncthreads();

    if (tid >= P_ * P_) return;

    const float* __restrict__ pafx = paf + ((size_t)b * (2*C_) + 2*c) * HW_;
    const float* __restrict__ pafy = pafx + HW_;

    const float delta = 1.0f / 9.0f;

    const int i = tid / P_;
    const int j = tid - i * P_;

    float axi = ax[i], ayi = ay[i];
    float dxl = bx[j] - axi;
    float dyl = by[j] - ayi;
    float norm = sqrtf(dxl*dxl + dyl*dyl) + 1e-8f;
    float vx = dxl / norm, vy = dyl / norm;

    int   idx[S_];
    bool  inb[S_];
    #pragma unroll
    for (int s = 0; s < S_; s++) {
        float t = (s == S_-1) ? 1.0f : (float)s * delta;
        float xs = axi + dxl * t;
        float ys = ayi + dyl * t;
        int xi = __float2int_rz(xs);
        int yi = __float2int_rz(ys);
        inb[s] = (xi >= 0) & (xi < W_) & (yi >= 0) & (yi < H_);
        int xc = min(max(xi, 0), W_ - 1);
        int yc = min(max(yi, 0), H_ - 1);
        idx[s] = yc * W_ + xc;
    }

    float pxv[S_], pyv[S_];
    #pragma unroll
    for (int s = 0; s < S_; s++) pxv[s] = __ldg(pafx + idx[s]);
    #pragma unroll
    for (int s = 0; s < S_; s++) pyv[s] = __ldg(pafy + idx[s]);

    float cnt = 0.0f, sum = 0.0f, cntp = 0.0f;
    #pragma unroll
    for (int s = 0; s < S_; s++) {
        float vs = pxv[s] * vx + pyv[s] * vy;
        if (inb[s]) {
            cnt += 1.0f;
            sum += vs;
            if (vs > PAF_SCORE_THRESH) cntp += 1.0f;
        }
    }

    float denom = fmaxf(cnt, 1.0f);
    float mean  = sum / denom;
    float ratio = cntp / denom;
    bool ok = (cnt > 0.0f) && (mean > 0.0f) && (ratio > PAF_COUNT_THRESH)
              && (sa[i] > PEAK_THRESH) && (sb[j] > PEAK_THRESH);
    float val = ok ? (mean + 0.5f * (sa[i] + sb[j])) : 0.0f;
    conn[(((size_t)b * C_ + c) * P_ + i) * P_ + j] = val;
}

// ---------------------------------------------------------------------------
extern "C" void kernel_launch(void* const* d_in, const int* in_sizes, int n_in,
                              void* d_out, int out_size)
{
    const float* heat = (const float*)d_in[0];
    const float* paf  = (const float*)d_in[1];
    if (n_in >= 2 && in_sizes[0] == B_ * 2 * C_ * HW_ && in_sizes[1] == B_ * K_ * HW_) {
        heat = (const float*)d_in[1];
        paf  = (const float*)d_in[0];
    }

    float* out_peaks = (float*)d_out;                      // B*K*P*3
    float* out_conn  = out_peaks + (size_t)B_ * K_ * P_ * 3;

    dim3 g1(H_ / RY, NCH);
    dim3 b1(QX, RY);
    peaks_scan<<<g1, b1>>>(heat);

    peaks_select<<<NCH, NT1>>>(heat, out_peaks);

    dim3 g2(C_, B_);
    conn_kernel<<<g2, NT2>>>(paf, out_peaks, out_conn);
}

// round 5
// speedup vs baseline: 2.8404x; 1.2390x over previous
#include <cuda_runtime.h>
#include <cstdint>
#include <cfloat>

#define B_  32
#define K_  17
#define H_  192
#define W_  192
#define C_  19
#define P_  20
#define S_  10
#define HW_ (H_*W_)
#define NCH (B_*K_)

#define PEAK_THRESH      0.1f
#define PAF_SCORE_THRESH 0.05f
#define PAF_COUNT_THRESH 0.8f

#define CAND_CAP 5120
#define SURV_CAP 512
#define NBINS    256
#define CTA_BUF  1536     // per-CTA staging; expected ~614 peaks/CTA

#define QX   48           // quads per row (192/4)
#define TY   8            // thread rows per CTA
#define RPT  4            // pixel rows per thread
#define CTAROWS (TY*RPT)  // 32 rows per CTA
#define NTS  (QX*TY)      // 384 threads

__constant__ int SKEL_A[C_] = {15,13,16,14,11, 5, 6, 5, 5, 6, 7, 8, 1, 0, 0, 1, 2, 3, 4};
__constant__ int SKEL_B[C_] = {13,11,14,12,12,11,12, 6, 7, 8, 9,10, 2, 1, 2, 3, 4, 5, 6};

// global scratch (zero-initialized at load; select restores zeros each run)
__device__ unsigned long long g_keys[NCH][CAND_CAP];
__device__ int g_count[NCH];
__device__ int g_hist[NCH][NBINS];

__device__ __forceinline__ float fmax3(float a, float b, float c) {
    return fmaxf(a, fmaxf(b, c));
}

// ---------------------------------------------------------------------------
// Kernel 1a: streaming peak scan. Thread = 4x4 pixel block, rolling rows.
// ---------------------------------------------------------------------------
__global__ __launch_bounds__(NTS)
void peaks_scan(const float* __restrict__ heat)
{
    const int bk = blockIdx.y;
    const float* __restrict__ h = heat + (size_t)bk * HW_;

    const int qx  = threadIdx.x;                        // 0..47
    const int y0  = blockIdx.x * CTAROWS + threadIdx.y * RPT;
    const int tid = threadIdx.y * QX + threadIdx.x;
    const int x0  = qx * 4;

    __shared__ unsigned long long s_buf[CTA_BUF];
    __shared__ int s_hist[NBINS];
    __shared__ int s_cnt;
    __shared__ int s_gbase;

    for (int i = tid; i < NBINS; i += NTS) s_hist[i] = 0;
    if (tid == 0) s_cnt = 0;
    __syncthreads();

    const bool has_l = (qx > 0);
    const bool has_r = (qx < QX - 1);

    // rolling state: rows y-1 (a) and y (b)
    float4 a, b;
    float la, ra, lb, rb;
    {
        const float* rw = h + (size_t)y0 * W_;
        b  = __ldg((const float4*)rw + qx);
        lb = has_l ? __ldg(rw + x0 - 1) : -FLT_MAX;
        rb = has_r ? __ldg(rw + x0 + 4) : -FLT_MAX;
        if (y0 > 0) {
            const float* ru = rw - W_;
            a  = __ldg((const float4*)ru + qx);
            la = has_l ? __ldg(ru + x0 - 1) : -FLT_MAX;
            ra = has_r ? __ldg(ru + x0 + 4) : -FLT_MAX;
        } else {
            a  = make_float4(-FLT_MAX, -FLT_MAX, -FLT_MAX, -FLT_MAX);
            la = -FLT_MAX; ra = -FLT_MAX;
        }
    }

    #pragma unroll
    for (int r = 0; r < RPT; r++) {
        const int y = y0 + r;
        float4 cn; float lc, rc;
        if (y + 1 < H_) {
            const float* rd = h + (size_t)(y + 1) * W_;
            cn = __ldg((const float4*)rd + qx);
            lc = has_l ? __ldg(rd + x0 - 1) : -FLT_MAX;
            rc = has_r ? __ldg(rd + x0 + 4) : -FLT_MAX;
        } else {
            cn = make_float4(-FLT_MAX, -FLT_MAX, -FLT_MAX, -FLT_MAX);
            lc = -FLT_MAX; rc = -FLT_MAX;
        }

        // vertical 3-max per column
        float v0 = fmax3(a.x, b.x, cn.x);
        float v1 = fmax3(a.y, b.y, cn.y);
        float v2 = fmax3(a.z, b.z, cn.z);
        float v3 = fmax3(a.w, b.w, cn.w);
        float vl = fmax3(la, lb, lc);
        float vr = fmax3(ra, rb, rc);

        // horizontal 3-windows (shared pairwise maxes)
        float m01 = fmaxf(v0, v1);
        float m23 = fmaxf(v2, v3);
        float w0 = fmaxf(vl,  m01);
        float w1 = fmaxf(m01, v2);
        float w2 = fmaxf(v1,  m23);
        float w3 = fmaxf(m23, vr);

        const float vv[4] = {b.x, b.y, b.z, b.w};
        const float ww[4] = {w0, w1, w2, w3};
        const int prow = y * W_ + x0;

        #pragma unroll
        for (int c = 0; c < 4; c++) {
            if (vv[c] > PEAK_THRESH && vv[c] >= ww[c]) {
                int pos = atomicAdd(&s_cnt, 1);
                if (pos < CTA_BUF) {
                    s_buf[pos] =
                        ((unsigned long long)__float_as_uint(vv[c]) << 32)
                        | (unsigned)(0xFFFFFFFFu - (unsigned)(prow + c));
                    int bin = min(NBINS - 1, (int)(vv[c] * (float)NBINS));
                    atomicAdd(&s_hist[bin], 1);
                }
            }
        }

        // shift rolling window
        a = b; b = cn;
        la = lb; lb = lc;
        ra = rb; rb = rc;
    }
    __syncthreads();

    const int n = min(s_cnt, CTA_BUF);
    if (tid == 0 && n > 0) s_gbase = atomicAdd(&g_count[bk], n);
    __syncthreads();

    if (n > 0) {
        const int gbase = s_gbase;
        for (int i = tid; i < n; i += NTS) {
            int pos = gbase + i;
            if (pos < CAND_CAP) g_keys[bk][pos] = s_buf[i];
        }
    }
    for (int i = tid; i < NBINS; i += NTS) {
        int hv = s_hist[i];
        if (hv) atomicAdd(&g_hist[bk][i], hv);   // fire-and-forget RED
    }
}

// ---------------------------------------------------------------------------
// Kernel 1b: per-channel top-20 selection + subpixel refine + scratch reset.
// ---------------------------------------------------------------------------
#define NT1 256
__global__ __launch_bounds__(NT1)
void peaks_select(const float* __restrict__ heat, float* __restrict__ out_peaks)
{
    const int bk = blockIdx.x;
    const float* __restrict__ h = heat + (size_t)bk * HW_;

    __shared__ unsigned long long surv[SURV_CAP];
    __shared__ int   s_hist[NBINS];
    __shared__ int   s_nsurv, s_tbin;
    __shared__ unsigned long long w_key[NT1/32];
    __shared__ int   w_slot[NT1/32];
    __shared__ unsigned long long sel_key[P_];

    const int tid  = threadIdx.x;
    const int lane = tid & 31;
    const int wid  = tid >> 5;

    const int nc = min(g_count[bk], CAND_CAP);

    // stage histogram in smem (coalesced), then cheap serial walk
    s_hist[tid] = g_hist[bk][tid];
    if (tid == 0) s_nsurv = 0;
    __syncthreads();

    if (tid == 0) {
        int need = min(P_, nc);
        int cum = 0, t = 0;
        if (need > 0) {
            for (int b = NBINS - 1; b >= 0; --b) {
                cum += s_hist[b];
                if (cum >= need) { t = b; break; }
            }
        }
        s_tbin = t;
    }
    __syncthreads();
    const int tbin = s_tbin;

    for (int i = tid; i < nc; i += NT1) {
        unsigned long long k = g_keys[bk][i];
        float sc = __uint_as_float((unsigned)(k >> 32));
        int bin = min(NBINS - 1, (int)(sc * (float)NBINS));
        if (bin >= tbin) {
            int slot = atomicAdd(&s_nsurv, 1);
            if (slot < SURV_CAP) surv[slot] = k;
        }
    }
    __syncthreads();

    unsigned long long* list;
    int len;
    if (s_nsurv <= SURV_CAP) { list = surv; len = s_nsurv; }
    else                     { list = &g_keys[bk][0]; len = nc; }  // fallback

    for (int r = 0; r < P_; r++) {
        unsigned long long bkey = 0ull;
        int bslot = -1;
        for (int i = tid; i < len; i += NT1) {
            unsigned long long k = list[i];
            if (k > bkey) { bkey = k; bslot = i; }
        }
        #pragma unroll
        for (int o = 16; o > 0; o >>= 1) {
            unsigned long long ok = __shfl_down_sync(0xffffffffu, bkey, o);
            int os = __shfl_down_sync(0xffffffffu, bslot, o);
            if (ok > bkey) { bkey = ok; bslot = os; }
        }
        if (lane == 0) { w_key[wid] = bkey; w_slot[wid] = bslot; }
        __syncthreads();
        if (tid == 0) {
            unsigned long long best = 0ull; int bsl = -1;
            #pragma unroll
            for (int w = 0; w < NT1/32; w++)
                if (w_key[w] > best) { best = w_key[w]; bsl = w_slot[w]; }
            sel_key[r] = best;
            if (bsl >= 0) list[bsl] = 0ull;
        }
        __syncthreads();
    }

    if (tid < P_) {
        unsigned long long k = sel_key[tid];
        float px = 0.0f, py = 0.0f, so = 0.0f;
        if (k != 0ull) {
            float sc = __uint_as_float((unsigned)(k >> 32));
            int p = (int)(0xFFFFFFFFu - (unsigned)(k & 0xFFFFFFFFull));
            int y = p / W_;
            int x = p - y * W_;
            float ddx = 0.0f, ddy = 0.0f;
            if (x > 0 && x < W_-1 && y > 0 && y < H_-1) {
                float c  = h[p];
                float rr = h[p + 1],  ll = h[p - 1];
                float dd = h[p + W_], uu = h[p - W_];
                float dx  = 0.5f * (rr - ll);
                float dxx = (rr + ll) - 2.0f * c;
                if (dxx != 0.0f) dx = dx / (-dxx);
                float dy  = 0.5f * (dd - uu);
                float dyy = (dd + uu) - 2.0f * c;
                if (dyy != 0.0f) dy = dy / (-dyy);
                ddx = dx; ddy = dy;
            }
            px = (float)x + ddx;
            py = (float)y + ddy;
            so = sc;
        }
        float* o = out_peaks + ((size_t)bk * P_ + tid) * 3;
        o[0] = px; o[1] = py; o[2] = so;
    }

    // reset scratch for the next (graph-replayed) run
    if (tid == 0) g_count[bk] = 0;
    g_hist[bk][tid] = 0;
}

// ---------------------------------------------------------------------------
// Kernel 2: per (b,c) edge — PAF line-integral scoring.
// ---------------------------------------------------------------------------
#define NT2 416
__global__ __launch_bounds__(NT2)
void conn_kernel(const float* __restrict__ paf,
                 const float* __restrict__ peaks,
                 float* __restrict__ conn)
{
    const int c = blockIdx.x;
    const int b = blockIdx.y;

    __shared__ float ax[P_], ay[P_], sa[P_];
    __shared__ float bx[P_], by[P_], sb[P_];

    const int tid = threadIdx.x;
    if (tid < 2 * P_) {
        int j = (tid < P_) ? tid : tid - P_;
        int joint = (tid < P_) ? SKEL_A[c] : SKEL_B[c];
        const float* pk = peaks + (((size_t)b * K_ + joint) * P_ + j) * 3;
        float x = pk[0], y = pk[1], s = pk[2];
        if (tid < P_) { ax[j] = x; ay[j] = y; sa[j] = s; }
        else          { bx[j] = x; by[j] = y; sb[j] = s; }
    }
    __syncthreads();

    if (tid >= P_ * P_) return;

    const float* __restrict__ pafx = paf + ((size_t)b * (2*C_) + 2*c) * HW_;
    const float* __restrict__ pafy = pafx + HW_;

    const float delta = 1.0f / 9.0f;

    const int i = tid / P_;
    const int j = tid - i * P_;

    float axi = ax[i], ayi = ay[i];
    float dxl = bx[j] - axi;
    float dyl = by[j] - ayi;
    float norm = sqrtf(dxl*dxl + dyl*dyl) + 1e-8f;
    float vx = dxl / norm, vy = dyl / norm;

    int   idx[S_];
    bool  inb[S_];
    #pragma unroll
    for (int s = 0; s < S_; s++) {
        float t = (s == S_-1) ? 1.0f : (float)s * delta;
        float xs = axi + dxl * t;
        float ys = ayi + dyl * t;
        int xi = __float2int_rz(xs);
        int yi = __float2int_rz(ys);
        inb[s] = (xi >= 0) & (xi < W_) & (yi >= 0) & (yi < H_);
        int xc = min(max(xi, 0), W_ - 1);
        int yc = min(max(yi, 0), H_ - 1);
        idx[s] = yc * W_ + xc;
    }

    float pxv[S_], pyv[S_];
    #pragma unroll
    for (int s = 0; s < S_; s++) pxv[s] = __ldg(pafx + idx[s]);
    #pragma unroll
    for (int s = 0; s < S_; s++) pyv[s] = __ldg(pafy + idx[s]);

    float cnt = 0.0f, sum = 0.0f, cntp = 0.0f;
    #pragma unroll
    for (int s = 0; s < S_; s++) {
        float vs = pxv[s] * vx + pyv[s] * vy;
        if (inb[s]) {
            cnt += 1.0f;
            sum += vs;
            if (vs > PAF_SCORE_THRESH) cntp += 1.0f;
        }
    }

    float denom = fmaxf(cnt, 1.0f);
    float mean  = sum / denom;
    float ratio = cntp / denom;
    bool ok = (cnt > 0.0f) && (mean > 0.0f) && (ratio > PAF_COUNT_THRESH)
              && (sa[i] > PEAK_THRESH) && (sb[j] > PEAK_THRESH);
    float val = ok ? (mean + 0.5f * (sa[i] + sb[j])) : 0.0f;
    conn[(((size_t)b * C_ + c) * P_ + i) * P_ + j] = val;
}

// ---------------------------------------------------------------------------
extern "C" void kernel_launch(void* const* d_in, const int* in_sizes, int n_in,
                              void* d_out, int out_size)
{
    const float* heat = (const float*)d_in[0];
    const float* paf  = (const float*)d_in[1];
    if (n_in >= 2 && in_sizes[0] == B_ * 2 * C_ * HW_ && in_sizes[1] == B_ * K_ * HW_) {
        heat = (const float*)d_in[1];
        paf  = (const float*)d_in[0];
    }

    float* out_peaks = (float*)d_out;                      // B*K*P*3
    float* out_conn  = out_peaks + (size_t)B_ * K_ * P_ * 3;

    dim3 g1(H_ / CTAROWS, NCH);
    dim3 b1(QX, TY);
    peaks_scan<<<g1, b1>>>(heat);

    peaks_select<<<NCH, NT1>>>(heat, out_peaks);

    dim3 g2(C_, B_);
    conn_kernel<<<g2, NT2>>>(paf, out_peaks, out_conn);
}

// round 6
// speedup vs baseline: 3.0364x; 1.0690x over previous
#include <cuda_runtime.h>
#include <cstdint>
#include <cfloat>

#define B_  32
#define K_  17
#define H_  192
#define W_  192
#define C_  19
#define P_  20
#define S_  10
#define HW_ (H_*W_)
#define NCH (B_*K_)

#define PEAK_THRESH      0.1f
#define PAF_SCORE_THRESH 0.05f
#define PAF_COUNT_THRESH 0.8f

#define CAND_CAP 5120
#define SURV_CAP 512
#define NBINS    256
#define CTA_BUF  1536     // per-CTA staging; expected ~683 peaks/CTA

#define QX   48           // quads per row (192/4)
#define TY   8            // thread rows per CTA
#define RPT  4            // pixel rows per thread
#define CTAROWS (TY*RPT)  // 32 rows per CTA
#define NTS  (QX*TY)      // 384 threads

__constant__ int SKEL_A[C_] = {15,13,16,14,11, 5, 6, 5, 5, 6, 7, 8, 1, 0, 0, 1, 2, 3, 4};
__constant__ int SKEL_B[C_] = {13,11,14,12,12,11,12, 6, 7, 8, 9,10, 2, 1, 2, 3, 4, 5, 6};

// global scratch (zero-initialized at load; select restores zeros each run)
__device__ unsigned long long g_keys[NCH][CAND_CAP];
__device__ int g_count[NCH];
__device__ int g_hist[NCH][NBINS];

__device__ __forceinline__ float fmax3(float a, float b, float c) {
    return fmaxf(a, fmaxf(b, c));
}

// ---------------------------------------------------------------------------
// Kernel 1a: streaming peak scan. Thread = 4x4 pixel block, rolling rows.
// Ballot-aggregated append: ONE shared atomic per warp-row.
// ---------------------------------------------------------------------------
__global__ __launch_bounds__(NTS)
void peaks_scan(const float* __restrict__ heat)
{
    const int bk = blockIdx.y;
    const float* __restrict__ h = heat + (size_t)bk * HW_;

    const int qx  = threadIdx.x;                        // 0..47
    const int y0  = blockIdx.x * CTAROWS + threadIdx.y * RPT;
    const int tid = threadIdx.y * QX + threadIdx.x;
    const int lane = tid & 31;
    const int x0  = qx * 4;

    __shared__ unsigned long long s_buf[CTA_BUF];
    __shared__ int s_hist[NBINS];
    __shared__ int s_cnt;
    __shared__ int s_gbase;

    for (int i = tid; i < NBINS; i += NTS) s_hist[i] = 0;
    if (tid == 0) s_cnt = 0;
    __syncthreads();

    const bool has_l = (qx > 0);
    const bool has_r = (qx < QX - 1);

    // rolling state: rows y-1 (a) and y (b)
    float4 a, b;
    float la, ra, lb, rb;
    {
        const float* rw = h + (size_t)y0 * W_;
        b  = __ldg((const float4*)rw + qx);
        lb = has_l ? __ldg(rw + x0 - 1) : -FLT_MAX;
        rb = has_r ? __ldg(rw + x0 + 4) : -FLT_MAX;
        if (y0 > 0) {
            const float* ru = rw - W_;
            a  = __ldg((const float4*)ru + qx);
            la = has_l ? __ldg(ru + x0 - 1) : -FLT_MAX;
            ra = has_r ? __ldg(ru + x0 + 4) : -FLT_MAX;
        } else {
            a  = make_float4(-FLT_MAX, -FLT_MAX, -FLT_MAX, -FLT_MAX);
            la = -FLT_MAX; ra = -FLT_MAX;
        }
    }

    #pragma unroll
    for (int r = 0; r < RPT; r++) {
        const int y = y0 + r;
        float4 cn; float lc, rc;
        if (y + 1 < H_) {
            const float* rd = h + (size_t)(y + 1) * W_;
            cn = __ldg((const float4*)rd + qx);
            lc = has_l ? __ldg(rd + x0 - 1) : -FLT_MAX;
            rc = has_r ? __ldg(rd + x0 + 4) : -FLT_MAX;
        } else {
            cn = make_float4(-FLT_MAX, -FLT_MAX, -FLT_MAX, -FLT_MAX);
            lc = -FLT_MAX; rc = -FLT_MAX;
        }

        // vertical 3-max per column
        float v0 = fmax3(a.x, b.x, cn.x);
        float v1 = fmax3(a.y, b.y, cn.y);
        float v2 = fmax3(a.z, b.z, cn.z);
        float v3 = fmax3(a.w, b.w, cn.w);
        float vl = fmax3(la, lb, lc);
        float vr = fmax3(ra, rb, rc);

        // horizontal 3-windows (shared pairwise maxes)
        float m01 = fmaxf(v0, v1);
        float m23 = fmaxf(v2, v3);
        float w0 = fmaxf(vl,  m01);
        float w1 = fmaxf(m01, v2);
        float w2 = fmaxf(v1,  m23);
        float w3 = fmaxf(m23, vr);

        const bool p0 = (b.x > PEAK_THRESH) && (b.x >= w0);
        const bool p1 = (b.y > PEAK_THRESH) && (b.y >= w1);
        const bool p2 = (b.z > PEAK_THRESH) && (b.z >= w2);
        const bool p3 = (b.w > PEAK_THRESH) && (b.w >= w3);

        unsigned m0 = __ballot_sync(0xffffffffu, p0);
        unsigned m1 = __ballot_sync(0xffffffffu, p1);
        unsigned m2 = __ballot_sync(0xffffffffu, p2);
        unsigned m3 = __ballot_sync(0xffffffffu, p3);
        int n0 = __popc(m0), n1 = __popc(m1), n2 = __popc(m2);
        int total = n0 + n1 + n2 + __popc(m3);

        if (total) {   // warp-uniform
            int base = 0;
            if (lane == 0) base = atomicAdd(&s_cnt, total);
            base = __shfl_sync(0xffffffffu, base, 0);
            const unsigned lt = (1u << lane) - 1u;
            const int prow = y * W_ + x0;
            #define STORE_PK(v, pos, pix)                                           \
                do { int _p = (pos);                                                \
                     if (_p < CTA_BUF) {                                            \
                         s_buf[_p] = ((unsigned long long)__float_as_uint(v) << 32) \
                                   | (unsigned)(0xFFFFFFFFu - (unsigned)(pix));     \
                         atomicAdd(&s_hist[min(NBINS-1, (int)((v)*(float)NBINS))], 1);\
                     } } while (0)
            if (p0) STORE_PK(b.x, base + __popc(m0 & lt),                 prow);
            if (p1) STORE_PK(b.y, base + n0 + __popc(m1 & lt),            prow + 1);
            if (p2) STORE_PK(b.z, base + n0 + n1 + __popc(m2 & lt),       prow + 2);
            if (p3) STORE_PK(b.w, base + n0 + n1 + n2 + __popc(m3 & lt),  prow + 3);
            #undef STORE_PK
        }

        // shift rolling window
        a = b; b = cn;
        la = lb; lb = lc;
        ra = rb; rb = rc;
    }
    __syncthreads();

    const int n = min(s_cnt, CTA_BUF);
    if (tid == 0 && n > 0) s_gbase = atomicAdd(&g_count[bk], n);
    __syncthreads();

    if (n > 0) {
        const int gbase = s_gbase;
        for (int i = tid; i < n; i += NTS) {
            int pos = gbase + i;
            if (pos < CAND_CAP) g_keys[bk][pos] = s_buf[i];
        }
    }
    for (int i = tid; i < NBINS; i += NTS) {
        int hv = s_hist[i];
        if (hv) atomicAdd(&g_hist[bk][i], hv);   // fire-and-forget RED
    }
}

// ---------------------------------------------------------------------------
// Kernel 1b: per-channel top-20 selection (warp-0, shfl-only rounds)
//            + subpixel refine + scratch reset.
// ---------------------------------------------------------------------------
#define NT1 256
__global__ __launch_bounds__(NT1)
void peaks_select(const float* __restrict__ heat, float* __restrict__ out_peaks)
{
    const int bk = blockIdx.x;
    const float* __restrict__ h = heat + (size_t)bk * HW_;

    __shared__ unsigned long long surv[SURV_CAP];
    __shared__ int   s_hist[NBINS];
    __shared__ int   s_nsurv, s_tbin;
    __shared__ unsigned long long sel_key[P_];

    const int tid  = threadIdx.x;
    const int lane = tid & 31;
    const int wid  = tid >> 5;

    const int nc = min(g_count[bk], CAND_CAP);

    // stage histogram in smem (coalesced), then cheap serial walk
    s_hist[tid] = g_hist[bk][tid];
    if (tid == 0) s_nsurv = 0;
    __syncthreads();

    if (tid == 0) {
        int need = min(P_, nc);
        int cum = 0, t = 0;
        if (need > 0) {
            for (int b = NBINS - 1; b >= 0; --b) {
                cum += s_hist[b];
                if (cum >= need) { t = b; break; }
            }
        }
        s_tbin = t;
    }
    __syncthreads();
    const int tbin = s_tbin;

    for (int i = tid; i < nc; i += NT1) {
        unsigned long long k = g_keys[bk][i];
        float sc = __uint_as_float((unsigned)(k >> 32));
        int bin = min(NBINS - 1, (int)(sc * (float)NBINS));
        if (bin >= tbin) {
            int slot = atomicAdd(&s_nsurv, 1);
            if (slot < SURV_CAP) surv[slot] = k;
        }
    }
    __syncthreads();

    // warp 0: 20 argmax rounds, shfl-only (no block barriers)
    if (wid == 0) {
        unsigned long long* list;
        int len;
        if (s_nsurv <= SURV_CAP) { list = surv; len = s_nsurv; }
        else                     { list = &g_keys[bk][0]; len = nc; } // fallback

        for (int r = 0; r < P_; r++) {
            unsigned long long bkey = 0ull;
            int bidx = -1;
            for (int i = lane; i < len; i += 32) {
                unsigned long long k = list[i];
                if (k > bkey) { bkey = k; bidx = i; }
            }
            #pragma unroll
            for (int o = 16; o > 0; o >>= 1) {
                unsigned long long ok = __shfl_down_sync(0xffffffffu, bkey, o);
                int oi = __shfl_down_sync(0xffffffffu, bidx, o);
                if (ok > bkey) { bkey = ok; bidx = oi; }
            }
            if (lane == 0) {
                sel_key[r] = bkey;
                if (bidx >= 0) list[bidx] = 0ull;
            }
            __syncwarp();
        }
    }
    __syncthreads();

    if (tid < P_) {
        unsigned long long k = sel_key[tid];
        float px = 0.0f, py = 0.0f, so = 0.0f;
        if (k != 0ull) {
            float sc = __uint_as_float((unsigned)(k >> 32));
            int p = (int)(0xFFFFFFFFu - (unsigned)(k & 0xFFFFFFFFull));
            int y = p / W_;
            int x = p - y * W_;
            float ddx = 0.0f, ddy = 0.0f;
            if (x > 0 && x < W_-1 && y > 0 && y < H_-1) {
                float c  = h[p];
                float rr = h[p + 1],  ll = h[p - 1];
                float dd = h[p + W_], uu = h[p - W_];
                float dx  = 0.5f * (rr - ll);
                float dxx = (rr + ll) - 2.0f * c;
                if (dxx != 0.0f) dx = dx / (-dxx);
                float dy  = 0.5f * (dd - uu);
                float dyy = (dd + uu) - 2.0f * c;
                if (dyy != 0.0f) dy = dy / (-dyy);
                ddx = dx; ddy = dy;
            }
            px = (float)x + ddx;
            py = (float)y + ddy;
            so = sc;
        }
        float* o = out_peaks + ((size_t)bk * P_ + tid) * 3;
        o[0] = px; o[1] = py; o[2] = so;
    }

    // reset scratch for the next (graph-replayed) run
    if (tid == 0) g_count[bk] = 0;
    g_hist[bk][tid] = 0;
}

// ---------------------------------------------------------------------------
// Kernel 2: flat one-thread-per-cell PAF line-integral scoring.
// ---------------------------------------------------------------------------
#define NT2 256
#define NCELLS (B_*C_*P_*P_)
__global__ __launch_bounds__(NT2)
void conn_kernel(const float* __restrict__ paf,
                 const float* __restrict__ peaks,
                 float* __restrict__ conn)
{
    const int gid = blockIdx.x * NT2 + threadIdx.x;
    if (gid >= NCELLS) return;

    int j = gid % P_;
    int t = gid / P_;
    int i = t % P_;  t /= P_;
    int c = t % C_;
    int b = t / C_;

    const float* pkA = peaks + (((size_t)b * K_ + SKEL_A[c]) * P_ + i) * 3;
    const float* pkB = peaks + (((size_t)b * K_ + SKEL_B[c]) * P_ + j) * 3;
    float axi = __ldg(pkA + 0), ayi = __ldg(pkA + 1), sa = __ldg(pkA + 2);
    float bxj = __ldg(pkB + 0), byj = __ldg(pkB + 1), sb = __ldg(pkB + 2);

    const float* __restrict__ pafx = paf + ((size_t)b * (2*C_) + 2*c) * HW_;
    const float* __restrict__ pafy = pafx + HW_;

    const float delta = 1.0f / 9.0f;

    float dxl = bxj - axi;
    float dyl = byj - ayi;
    float norm = sqrtf(dxl*dxl + dyl*dyl) + 1e-8f;
    float vx = dxl / norm, vy = dyl / norm;

    int   idx[S_];
    bool  inb[S_];
    #pragma unroll
    for (int s = 0; s < S_; s++) {
        float t2 = (s == S_-1) ? 1.0f : (float)s * delta;
        float xs = axi + dxl * t2;
        float ys = ayi + dyl * t2;
        int xi = __float2int_rz(xs);
        int yi = __float2int_rz(ys);
        inb[s] = (xi >= 0) & (xi < W_) & (yi >= 0) & (yi < H_);
        int xc = min(max(xi, 0), W_ - 1);
        int yc = min(max(yi, 0), H_ - 1);
        idx[s] = yc * W_ + xc;
    }

    float pxv[S_], pyv[S_];
    #pragma unroll
    for (int s = 0; s < S_; s++) pxv[s] = __ldg(pafx + idx[s]);
    #pragma unroll
    for (int s = 0; s < S_; s++) pyv[s] = __ldg(pafy + idx[s]);

    float cnt = 0.0f, sum = 0.0f, cntp = 0.0f;
    #pragma unroll
    for (int s = 0; s < S_; s++) {
        float vs = pxv[s] * vx + pyv[s] * vy;
        if (inb[s]) {
            cnt += 1.0f;
            sum += vs;
            if (vs > PAF_SCORE_THRESH) cntp += 1.0f;
        }
    }

    float denom = fmaxf(cnt, 1.0f);
    float mean  = sum / denom;
    float ratio = cntp / denom;
    bool ok = (cnt > 0.0f) && (mean > 0.0f) && (ratio > PAF_COUNT_THRESH)
              && (sa > PEAK_THRESH) && (sb > PEAK_THRESH);
    conn[gid] = ok ? (mean + 0.5f * (sa + sb)) : 0.0f;
}

// ---------------------------------------------------------------------------
extern "C" void kernel_launch(void* const* d_in, const int* in_sizes, int n_in,
                              void* d_out, int out_size)
{
    const float* heat = (const float*)d_in[0];
    const float* paf  = (const float*)d_in[1];
    if (n_in >= 2 && in_sizes[0] == B_ * 2 * C_ * HW_ && in_sizes[1] == B_ * K_ * HW_) {
        heat = (const float*)d_in[1];
        paf  = (const float*)d_in[0];
    }

    float* out_peaks = (float*)d_out;                      // B*K*P*3
    float* out_conn  = out_peaks + (size_t)B_ * K_ * P_ * 3;

    dim3 g1(H_ / CTAROWS, NCH);
    dim3 b1(QX, TY);
    peaks_scan<<<g1, b1>>>(heat);

    peaks_select<<<NCH, NT1>>>(heat, out_peaks);

    conn_kernel<<<(NCELLS + NT2 - 1) / NT2, NT2>>>(paf, out_peaks, out_conn);
}